// round 6
// baseline (speedup 1.0000x reference)
#include <cuda_runtime.h>
#include <cuda_bf16.h>
#include <math.h>
#include <stdint.h>

// ---------------------------------------------------------------- problem dims
#define FDIM 1024
#define NK   256
#define NL   8
#define KLD  2048            // NK*NL
#define BTD  32768           // B*T
#define KCB  2048            // row stride in BYTES of quantized A/W ([x | x^2] int8)

// ---------------------------------------------------------------- GEMM tiling
#define BM 128
#define BN 256
#define BKB 128              // K-bytes per stage (= 128 int8 k-elems)
#define NTHREADS 256
#define STAGES 3
#define STAGE_BYTES (48 * 1024)           // A 16KB + B 32KB
#define SM_BIAS_OFF (STAGES * STAGE_BYTES)
#define SM_SW_OFF   (SM_BIAS_OFF + BN * 4)
#define SMEM_TOTAL  (SM_SW_OFF + BN * 4)  // 149504 B

#define ALPHA 8.0f           // scale equalizer for the x^2 half (fallback path)

// ---------------------------------------------------------------- device scratch
__device__ int8_t g_Aq[(size_t)BTD * KCB];   // 64 MB  [x_q | x2_q]
__device__ int8_t g_Wq[(size_t)KLD * KCB];   // 4 MB   [w_q | w2_q]
__device__ float  g_bias[KLD];
__device__ float  g_sW[KLD];                 // per-(k,l) W scale
__device__ float  g_sA[BTD];                 // per-row X scale
__device__ float  g_w2[FDIM];                // -0.5*exp(-log_cov[0][f]) fp32
__device__ float  g_q[BTD];                  // per-row x^2 term when uniform
__device__ int    g_uniform;

// ---------------------------------------------------------------- asm helpers
__device__ __forceinline__ uint32_t smem_u32(const void* p) {
    uint32_t a;
    asm("{ .reg .u64 t; cvta.to.shared.u64 t, %1; cvt.u32.u64 %0, t; }" : "=r"(a) : "l"(p));
    return a;
}
__device__ __forceinline__ void cp16(uint32_t dst, const void* src) {
    asm volatile("cp.async.cg.shared.global [%0], [%1], 16;" :: "r"(dst), "l"(src));
}
#define CP_COMMIT() asm volatile("cp.async.commit_group;" ::: "memory")
#define CP_WAIT(n)  asm volatile("cp.async.wait_group %0;" :: "n"(n) : "memory")

#define LDSM4(r, addr)                                                           \
    asm volatile("ldmatrix.sync.aligned.m8n8.x4.shared.b16 {%0,%1,%2,%3}, [%4];" \
        : "=r"((r)[0]), "=r"((r)[1]), "=r"((r)[2]), "=r"((r)[3]) : "r"(addr))

#define MMAI8(c, a, b0, b1)                                                      \
    asm volatile("mma.sync.aligned.m16n8k32.row.col.s32.s8.s8.s32 "              \
        "{%0,%1,%2,%3}, {%4,%5,%6,%7}, {%8,%9}, {%0,%1,%2,%3};"                  \
        : "+r"((c)[0]), "+r"((c)[1]), "+r"((c)[2]), "+r"((c)[3])                 \
        : "r"((a)[0]), "r"((a)[1]), "r"((a)[2]), "r"((a)[3]), "r"(b0), "r"(b1))

// ---------------------------------------------------------------- fast math
__device__ __forceinline__ float fast_exp(float u) {   // e^u, u <= 0
    u = fmaxf(u, -60.0f);
    float z  = u * 1.4426950408889634f;
    float nf = rintf(z);
    float w  = fmaf(nf, -0.6931471805599453f, u);
    float p  = fmaf(w, 0.041666668f, 0.16666667f);
    p = fmaf(w, p, 0.5f);
    p = fmaf(w, p, 1.0f);
    p = fmaf(w, p, 1.0f);
    return p * __int_as_float(((int)nf + 127) << 23);
}
__device__ __forceinline__ float fast_log(float s) {   // ln(s), s in [1, 16]
    int ib = __float_as_int(s);
    int e  = (ib - 0x3f3504f3) >> 23;
    float m = __int_as_float(ib - (e << 23));
    float t = m - 1.0f;
    float p = -0.125f;
    p = fmaf(p, t, 0.14285714f);
    p = fmaf(p, t, -0.16666667f);
    p = fmaf(p, t, 0.2f);
    p = fmaf(p, t, -0.25f);
    p = fmaf(p, t, 0.33333333f);
    p = fmaf(p, t, -0.5f);
    p = fmaf(p, t, 1.0f);
    p = p * t;
    return fmaf((float)e, 0.6931471805599453f, p);
}

__device__ __forceinline__ int8_t q8(float v, float inv) {
    int q = __float2int_rn(v * inv);
    q = max(-127, min(127, q));
    return (int8_t)q;
}
__device__ __forceinline__ uint32_t pack4(int8_t a, int8_t b, int8_t c, int8_t d) {
    return (uint32_t)(uint8_t)a | ((uint32_t)(uint8_t)b << 8) |
           ((uint32_t)(uint8_t)c << 16) | ((uint32_t)(uint8_t)d << 24);
}

// ---------------------------------------------------------------- prep kernels
__global__ void initFlagW2(const float* __restrict__ log_cov) {
    int f = blockIdx.x * blockDim.x + threadIdx.x;
    if (f == 0) g_uniform = 1;
    g_w2[f] = -0.5f * expf(-log_cov[f]);
}

// uniform iff every log_cov row is bitwise identical to row 0
__global__ void checkUni(const float* __restrict__ log_cov) {
    int kl = blockIdx.x + 1, t = threadIdx.x;
    const uint4* a = reinterpret_cast<const uint4*>(log_cov + (size_t)kl * FDIM);
    const uint4* b = reinterpret_cast<const uint4*>(log_cov);
    uint4 x = a[t], y = b[t];
    bool ok = (x.x == y.x) && (x.y == y.y) && (x.z == y.z) && (x.w == y.w);
    if (!__syncthreads_and(ok)) {
        if (t == 0) atomicAnd(&g_uniform, 0);
    }
}

// per (k,l): quantize w = mu*iv (and w2 = -0.5*iv if fallback), bias pieces.
__global__ void prepW(const float* __restrict__ mu, const float* __restrict__ log_cov) {
    int kl = blockIdx.x, t = threadIdx.x;
    bool uni = (g_uniform != 0);
    const float* mu_r = mu + (size_t)kl * FDIM;
    const float* lc_r = log_cov + (size_t)kl * FDIM;
    int8_t* wq = g_Wq + (size_t)kl * KCB;

    float w[4], w2[4];
    float s_lc = 0.f, s_m2 = 0.f, am = 0.f;
#pragma unroll
    for (int j = 0; j < 4; j++) {
        int f = t * 4 + j;
        float lc = lc_r[f];
        float iv = expf(-lc);
        float m  = mu_r[f];
        w[j]  = m * iv;
        w2[j] = -0.5f * iv;
        s_lc += lc;
        s_m2 += m * m * iv;
        am = fmaxf(am, fabsf(w[j]));
    }
    __shared__ float sh0[256], sh1[256], shm[256];
    sh0[t] = s_lc; sh1[t] = s_m2; shm[t] = am;
    __syncthreads();
    for (int s = 128; s > 0; s >>= 1) {
        if (t < s) {
            sh0[t] += sh0[t + s];
            sh1[t] += sh1[t + s];
            shm[t] = fmaxf(shm[t], shm[t + s]);
        }
        __syncthreads();
    }
    float absmax = fmaxf(shm[0], 1e-20f);
    float sw = absmax / 127.0f;
    float inv = 127.0f / absmax;
    *reinterpret_cast<uint32_t*>(wq + t * 4) =
        pack4(q8(w[0], inv), q8(w[1], inv), q8(w[2], inv), q8(w[3], inv));
    if (!uni) {
        float inv2 = inv * ALPHA;
        *reinterpret_cast<uint32_t*>(wq + FDIM + t * 4) =
            pack4(q8(w2[0], inv2), q8(w2[1], inv2), q8(w2[2], inv2), q8(w2[3], inv2));
    }
    if (t == 0) {
        g_sW[kl] = sw;
        g_bias[kl] = -0.5f * (float)FDIM * 1.8378770664093453f - 0.5f * sh0[0] - 0.5f * sh1[0];
    }
}

__global__ void prepPi(const float* __restrict__ log_pi) {
    int k = blockIdx.x * blockDim.x + threadIdx.x;
    if (k >= NK) return;
    float v[NL], mx = -INFINITY;
#pragma unroll
    for (int l = 0; l < NL; l++) { v[l] = log_pi[k * NL + l]; mx = fmaxf(mx, v[l]); }
    float s = 0.f;
#pragma unroll
    for (int l = 0; l < NL; l++) s += expf(v[l] - mx);
    float lse = mx + logf(s);
#pragma unroll
    for (int l = 0; l < NL; l++) g_bias[k * NL + l] += v[l] - lse;
}

// warp-per-row: absmax -> quantize X (+ X^2 if fallback), q[row], scale.
// No smem, no __syncthreads. 8 warps per block = 8 rows.
__global__ void prepA(const float* __restrict__ X) {
    int lane = threadIdx.x & 31;
    int row  = blockIdx.x * 8 + (threadIdx.x >> 5);
    bool uni = (g_uniform != 0);

    const float4* xr = reinterpret_cast<const float4*>(X) + (size_t)row * 256;
    float4 v[8];
    float am = 0.f;
#pragma unroll
    for (int j = 0; j < 8; j++) {
        v[j] = xr[lane + j * 32];
        am = fmaxf(am, fmaxf(fmaxf(fabsf(v[j].x), fabsf(v[j].y)),
                             fmaxf(fabsf(v[j].z), fabsf(v[j].w))));
    }
#pragma unroll
    for (int o = 16; o > 0; o >>= 1) am = fmaxf(am, __shfl_xor_sync(0xffffffffu, am, o));
    float absmax = fmaxf(am, 1e-20f);
    float inv = 127.0f / absmax;

    int8_t* aq = g_Aq + (size_t)row * KCB;
    float q = 0.f;
#pragma unroll
    for (int j = 0; j < 8; j++) {
        *reinterpret_cast<uint32_t*>(aq + (lane + j * 32) * 4) =
            pack4(q8(v[j].x, inv), q8(v[j].y, inv), q8(v[j].z, inv), q8(v[j].w, inv));
        if (uni) {
            const float4 w = reinterpret_cast<const float4*>(g_w2)[lane + j * 32];
            q += v[j].x * v[j].x * w.x + v[j].y * v[j].y * w.y
               + v[j].z * v[j].z * w.z + v[j].w * v[j].w * w.w;
        } else {
            float inv2 = inv / ALPHA;
            *reinterpret_cast<uint32_t*>(aq + FDIM + (lane + j * 32) * 4) =
                pack4(q8(v[j].x * v[j].x, inv2), q8(v[j].y * v[j].y, inv2),
                      q8(v[j].z * v[j].z, inv2), q8(v[j].w * v[j].w, inv2));
        }
    }
#pragma unroll
    for (int o = 16; o > 0; o >>= 1) q += __shfl_xor_sync(0xffffffffu, q, o);
    if (lane == 0) {
        g_q[row]  = q;
        g_sA[row] = absmax / 127.0f;
    }
}

// ---------------------------------------------------------------- stage loader
// A tile: 128 rows x 128B @ stage+0; B tile: 256 rows x 128B @ stage+16KB.
__device__ __forceinline__ void issue_stage(uint32_t smStage,
                                            const int8_t* gA, const int8_t* gB,
                                            int kByte, int tid) {
    const int8_t* a = gA + kByte;
    const int8_t* b = gB + kByte;
#pragma unroll
    for (int i = 0; i < 4; i++) {
        int id  = tid + i * NTHREADS;          // 0..1023  (A: 128 rows x 8 ch)
        int row = id >> 3, ch = id & 7;
        uint32_t dst = smStage + row * 128 + ((ch ^ (row & 7)) << 4);
        cp16(dst, a + (size_t)row * KCB + ch * 16);
    }
#pragma unroll
    for (int i = 0; i < 8; i++) {
        int id  = tid + i * NTHREADS;          // 0..2047  (B: 256 rows x 8 ch)
        int row = id >> 3, ch = id & 7;
        uint32_t dst = smStage + 16384 + row * 128 + ((ch ^ (row & 7)) << 4);
        cp16(dst, b + (size_t)row * KCB + ch * 16);
    }
    CP_COMMIT();
}

// ---------------------------------------------------------------- main kernel
// Block 128x256, 8 warps in 2(M) x 4(N), warp tile 64x64.
__global__ __launch_bounds__(NTHREADS, 1)
void gmm_main(float* __restrict__ out) {
    extern __shared__ char smem[];
    uint32_t sb = smem_u32(smem);
    float* sBias = reinterpret_cast<float*>(smem + SM_BIAS_OFF);
    float* sSw   = reinterpret_cast<float*>(smem + SM_SW_OFF);

    int tid  = threadIdx.x;
    int wid  = tid >> 5, lane = tid & 31;
    int wm   = wid & 1;          // 2 warps over M -> 64 rows each
    int wn   = wid >> 1;         // 4 warps over N -> 64 cols each

    int rowBase = blockIdx.y * BM;
    int colBase = blockIdx.x * BN;
    int kIters  = (g_uniform != 0) ? 8 : 16;

    sBias[tid] = g_bias[colBase + tid];
    sSw[tid]   = g_sW[colBase + tid];

    const int8_t* gA = g_Aq + (size_t)rowBase * KCB;
    const int8_t* gB = g_Wq + (size_t)colBase * KCB;

    issue_stage(sb + 0 * STAGE_BYTES, gA, gB, 0 * BKB, tid);
    issue_stage(sb + 1 * STAGE_BYTES, gA, gB, 1 * BKB, tid);

    int acc[4][8][4];
#pragma unroll
    for (int mt = 0; mt < 4; mt++)
#pragma unroll
        for (int nt = 0; nt < 8; nt++)
#pragma unroll
            for (int j = 0; j < 4; j++) acc[mt][nt][j] = 0;

    // per-lane swizzled base offsets (XOR-composable with ks<<5)
    int cHi = lane >> 4;
    uint32_t offA[4], offB[4];
#pragma unroll
    for (int mt = 0; mt < 4; mt++) {
        int r = wm * 64 + (lane & 15) + mt * 16;
        offA[mt] = (uint32_t)(r * 128) + (uint32_t)(((cHi ^ (r & 7))) << 4);
    }
#pragma unroll
    for (int p = 0; p < 4; p++) {
        int r = wn * 64 + (lane & 15) + p * 16;
        offB[p] = (uint32_t)(16384 + r * 128) + (uint32_t)(((cHi ^ (r & 7))) << 4);
    }

#pragma unroll 1
    for (int s = 0; s < kIters; s++) {
        if (s == kIters - 1) CP_WAIT(0); else CP_WAIT(1);
        __syncthreads();

        uint32_t smStage = sb + (uint32_t)(s % 3) * STAGE_BYTES;

        if (s + 2 < kIters)
            issue_stage(sb + (uint32_t)((s + 2) % 3) * STAGE_BYTES, gA, gB, (s + 2) * BKB, tid);

        uint32_t bA0 = smStage + offA[0], bA1 = smStage + offA[1];
        uint32_t bA2 = smStage + offA[2], bA3 = smStage + offA[3];
        uint32_t bB0 = smStage + offB[0], bB1 = smStage + offB[1];
        uint32_t bB2 = smStage + offB[2], bB3 = smStage + offB[3];

#pragma unroll
        for (int ks = 0; ks < 4; ks++) {       // each ks = 32 int8 k-elems
            uint32_t kx = (uint32_t)ks << 5;
            uint32_t a[4][4], b[4][4];
            LDSM4(a[0], bA0 ^ kx);
            LDSM4(a[1], bA1 ^ kx);
            LDSM4(a[2], bA2 ^ kx);
            LDSM4(a[3], bA3 ^ kx);
            LDSM4(b[0], bB0 ^ kx);
            LDSM4(b[1], bB1 ^ kx);
            LDSM4(b[2], bB2 ^ kx);
            LDSM4(b[3], bB3 ^ kx);
#pragma unroll
            for (int mt = 0; mt < 4; mt++)
#pragma unroll
                for (int nt = 0; nt < 8; nt++) {
                    int p = nt >> 1, q = nt & 1;
                    MMAI8(acc[mt][nt], a[mt], b[p][q], b[p][q + 2]);
                }
        }
    }
    __syncthreads();

    // ------------- epilogue: dequant + bias + logsumexp(8) + q[row]
    int colq = (lane & 3) * 2;
    int kBase = (colBase >> 3) + wn * 8;
#pragma unroll
    for (int mt = 0; mt < 4; mt++) {
#pragma unroll
        for (int h = 0; h < 2; h++) {
            int row = rowBase + wm * 64 + mt * 16 + h * 8 + (lane >> 2);
            float sxr = g_sA[row];
            float qr  = g_q[row];
#pragma unroll
            for (int nt = 0; nt < 8; nt++) {
                int c0 = wn * 64 + nt * 8 + colq;
                float sc0 = sSw[c0] * sxr;
                float sc1 = sSw[c0 + 1] * sxr;
                float l0 = (float)acc[mt][nt][h * 2]     * sc0 + sBias[c0];
                float l1 = (float)acc[mt][nt][h * 2 + 1] * sc1 + sBias[c0 + 1];
                float m = fmaxf(l0, l1);
                m = fmaxf(m, __shfl_xor_sync(0xffffffffu, m, 1));
                m = fmaxf(m, __shfl_xor_sync(0xffffffffu, m, 2));
                float sum = fast_exp(l0 - m) + fast_exp(l1 - m);
                sum += __shfl_xor_sync(0xffffffffu, sum, 1);
                sum += __shfl_xor_sync(0xffffffffu, sum, 2);
                if ((lane & 3) == 0)
                    out[(size_t)row * NK + kBase + nt] = m + fast_log(sum) + qr;
            }
        }
    }
}

// ---------------------------------------------------------------- launch
extern "C" void kernel_launch(void* const* d_in, const int* in_sizes, int n_in,
                              void* d_out, int out_size) {
    const float* X       = (const float*)d_in[0];
    const float* mu      = (const float*)d_in[1];
    const float* log_cov = (const float*)d_in[2];
    const float* log_pi  = (const float*)d_in[3];
    float* out = (float*)d_out;

    cudaFuncSetAttribute(gmm_main, cudaFuncAttributeMaxDynamicSharedMemorySize, SMEM_TOTAL);

    initFlagW2<<<FDIM / 256, 256>>>(log_cov);
    checkUni<<<KLD - 1, 256>>>(log_cov);
    prepW<<<KLD, 256>>>(mu, log_cov);
    prepA<<<BTD / 8, 256>>>(X);
    prepPi<<<1, 256>>>(log_pi);

    dim3 grid(KLD / BN, BTD / BM);   // (8, 256)
    gmm_main<<<grid, NTHREADS, SMEM_TOTAL>>>(out);
}

// round 7
// speedup vs baseline: 1.2019x; 1.2019x over previous
#include <cuda_runtime.h>
#include <cuda_bf16.h>
#include <math.h>
#include <stdint.h>

// ---------------------------------------------------------------- problem dims
#define FDIM 1024
#define NK   256
#define NL   8
#define KLD  2048            // NK*NL
#define BTD  32768           // B*T
#define KCB  2048            // row stride in BYTES of quantized A/W ([x | x^2] int8)

// ---------------------------------------------------------------- GEMM tiling
#define BM 128
#define BN 256
#define BKB 128              // K-bytes per stage (= 128 int8 k-elems)
#define NTHREADS 512         // 16 warps: 4(M) x 4(N), warp tile 32x64
#define STAGES 4
#define STAGE_BYTES (48 * 1024)           // A 16KB + B 32KB
#define SM_BIAS_OFF (STAGES * STAGE_BYTES)
#define SM_SW_OFF   (SM_BIAS_OFF + BN * 4)
#define SMEM_TOTAL  (SM_SW_OFF + BN * 4)  // 198656 B

#define ALPHA 8.0f           // scale equalizer for the x^2 half (fallback path)

// ---------------------------------------------------------------- device scratch
__device__ int8_t g_Aq[(size_t)BTD * KCB];   // 64 MB  [x_q | x2_q]
__device__ int8_t g_Wq[(size_t)KLD * KCB];   // 4 MB   [w_q | w2_q]
__device__ float  g_bias[KLD];
__device__ float  g_sW[KLD];                 // per-(k,l) W scale
__device__ float  g_sA[BTD];                 // per-row X scale
__device__ float  g_w2[FDIM];                // -0.5*exp(-log_cov[0][f]) fp32
__device__ float  g_q[BTD];                  // per-row x^2 term when uniform
__device__ int    g_uniform;

// ---------------------------------------------------------------- asm helpers
__device__ __forceinline__ uint32_t smem_u32(const void* p) {
    uint32_t a;
    asm("{ .reg .u64 t; cvta.to.shared.u64 t, %1; cvt.u32.u64 %0, t; }" : "=r"(a) : "l"(p));
    return a;
}
__device__ __forceinline__ void cp16(uint32_t dst, const void* src) {
    asm volatile("cp.async.cg.shared.global [%0], [%1], 16;" :: "r"(dst), "l"(src));
}
#define CP_COMMIT() asm volatile("cp.async.commit_group;" ::: "memory")
#define CP_WAIT(n)  asm volatile("cp.async.wait_group %0;" :: "n"(n) : "memory")

#define LDSM4(r, addr)                                                           \
    asm volatile("ldmatrix.sync.aligned.m8n8.x4.shared.b16 {%0,%1,%2,%3}, [%4];" \
        : "=r"((r)[0]), "=r"((r)[1]), "=r"((r)[2]), "=r"((r)[3]) : "r"(addr))

#define MMAI8(c, a, b0, b1)                                                      \
    asm volatile("mma.sync.aligned.m16n8k32.row.col.s32.s8.s8.s32 "              \
        "{%0,%1,%2,%3}, {%4,%5,%6,%7}, {%8,%9}, {%0,%1,%2,%3};"                  \
        : "+r"((c)[0]), "+r"((c)[1]), "+r"((c)[2]), "+r"((c)[3])                 \
        : "r"((a)[0]), "r"((a)[1]), "r"((a)[2]), "r"((a)[3]), "r"(b0), "r"(b1))

// ---------------------------------------------------------------- fast math
__device__ __forceinline__ float fast_exp(float u) {   // e^u, u <= 0
    u = fmaxf(u, -60.0f);
    float z  = u * 1.4426950408889634f;
    float nf = rintf(z);
    float w  = fmaf(nf, -0.6931471805599453f, u);
    float p  = fmaf(w, 0.041666668f, 0.16666667f);
    p = fmaf(w, p, 0.5f);
    p = fmaf(w, p, 1.0f);
    p = fmaf(w, p, 1.0f);
    return p * __int_as_float(((int)nf + 127) << 23);
}
__device__ __forceinline__ float fast_log(float s) {   // ln(s), s in [1, 16]
    int ib = __float_as_int(s);
    int e  = (ib - 0x3f3504f3) >> 23;
    float m = __int_as_float(ib - (e << 23));
    float t = m - 1.0f;
    float p = -0.125f;
    p = fmaf(p, t, 0.14285714f);
    p = fmaf(p, t, -0.16666667f);
    p = fmaf(p, t, 0.2f);
    p = fmaf(p, t, -0.25f);
    p = fmaf(p, t, 0.33333333f);
    p = fmaf(p, t, -0.5f);
    p = fmaf(p, t, 1.0f);
    p = p * t;
    return fmaf((float)e, 0.6931471805599453f, p);
}

__device__ __forceinline__ int8_t q8(float v, float inv) {
    int q = __float2int_rn(v * inv);
    q = max(-127, min(127, q));
    return (int8_t)q;
}
__device__ __forceinline__ uint32_t pack4(int8_t a, int8_t b, int8_t c, int8_t d) {
    return (uint32_t)(uint8_t)a | ((uint32_t)(uint8_t)b << 8) |
           ((uint32_t)(uint8_t)c << 16) | ((uint32_t)(uint8_t)d << 24);
}

// ---------------------------------------------------------------- prep kernels
__global__ void initFlagW2(const float* __restrict__ log_cov) {
    int f = blockIdx.x * blockDim.x + threadIdx.x;
    if (f == 0) g_uniform = 1;
    g_w2[f] = -0.5f * expf(-log_cov[f]);
}

// uniform iff every log_cov row is bitwise identical to row 0
__global__ void checkUni(const float* __restrict__ log_cov) {
    int kl = blockIdx.x + 1, t = threadIdx.x;
    const uint4* a = reinterpret_cast<const uint4*>(log_cov + (size_t)kl * FDIM);
    const uint4* b = reinterpret_cast<const uint4*>(log_cov);
    uint4 x = a[t], y = b[t];
    bool ok = (x.x == y.x) && (x.y == y.y) && (x.z == y.z) && (x.w == y.w);
    if (!__syncthreads_and(ok)) {
        if (t == 0) atomicAnd(&g_uniform, 0);
    }
}

// per (k,l): quantize w = mu*iv (and w2 = -0.5*iv if fallback), bias pieces.
__global__ void prepW(const float* __restrict__ mu, const float* __restrict__ log_cov) {
    int kl = blockIdx.x, t = threadIdx.x;
    bool uni = (g_uniform != 0);
    const float* mu_r = mu + (size_t)kl * FDIM;
    const float* lc_r = log_cov + (size_t)kl * FDIM;
    int8_t* wq = g_Wq + (size_t)kl * KCB;

    float w[4], w2[4];
    float s_lc = 0.f, s_m2 = 0.f, am = 0.f;
#pragma unroll
    for (int j = 0; j < 4; j++) {
        int f = t * 4 + j;
        float lc = lc_r[f];
        float iv = expf(-lc);
        float m  = mu_r[f];
        w[j]  = m * iv;
        w2[j] = -0.5f * iv;
        s_lc += lc;
        s_m2 += m * m * iv;
        am = fmaxf(am, fabsf(w[j]));
    }
    __shared__ float sh0[256], sh1[256], shm[256];
    sh0[t] = s_lc; sh1[t] = s_m2; shm[t] = am;
    __syncthreads();
    for (int s = 128; s > 0; s >>= 1) {
        if (t < s) {
            sh0[t] += sh0[t + s];
            sh1[t] += sh1[t + s];
            shm[t] = fmaxf(shm[t], shm[t + s]);
        }
        __syncthreads();
    }
    float absmax = fmaxf(shm[0], 1e-20f);
    float sw = absmax / 127.0f;
    float inv = 127.0f / absmax;
    *reinterpret_cast<uint32_t*>(wq + t * 4) =
        pack4(q8(w[0], inv), q8(w[1], inv), q8(w[2], inv), q8(w[3], inv));
    if (!uni) {
        float inv2 = inv * ALPHA;
        *reinterpret_cast<uint32_t*>(wq + FDIM + t * 4) =
            pack4(q8(w2[0], inv2), q8(w2[1], inv2), q8(w2[2], inv2), q8(w2[3], inv2));
    }
    if (t == 0) {
        g_sW[kl] = sw;
        g_bias[kl] = -0.5f * (float)FDIM * 1.8378770664093453f - 0.5f * sh0[0] - 0.5f * sh1[0];
    }
}

__global__ void prepPi(const float* __restrict__ log_pi) {
    int k = blockIdx.x * blockDim.x + threadIdx.x;
    if (k >= NK) return;
    float v[NL], mx = -INFINITY;
#pragma unroll
    for (int l = 0; l < NL; l++) { v[l] = log_pi[k * NL + l]; mx = fmaxf(mx, v[l]); }
    float s = 0.f;
#pragma unroll
    for (int l = 0; l < NL; l++) s += expf(v[l] - mx);
    float lse = mx + logf(s);
#pragma unroll
    for (int l = 0; l < NL; l++) g_bias[k * NL + l] += v[l] - lse;
}

// warp-per-row: absmax -> quantize X (+ X^2 if fallback), q[row], scale.
__global__ void prepA(const float* __restrict__ X) {
    int lane = threadIdx.x & 31;
    int row  = blockIdx.x * 8 + (threadIdx.x >> 5);
    bool uni = (g_uniform != 0);

    const float4* xr = reinterpret_cast<const float4*>(X) + (size_t)row * 256;
    float4 v[8];
    float am = 0.f;
#pragma unroll
    for (int j = 0; j < 8; j++) {
        v[j] = xr[lane + j * 32];
        am = fmaxf(am, fmaxf(fmaxf(fabsf(v[j].x), fabsf(v[j].y)),
                             fmaxf(fabsf(v[j].z), fabsf(v[j].w))));
    }
#pragma unroll
    for (int o = 16; o > 0; o >>= 1) am = fmaxf(am, __shfl_xor_sync(0xffffffffu, am, o));
    float absmax = fmaxf(am, 1e-20f);
    float inv = 127.0f / absmax;

    int8_t* aq = g_Aq + (size_t)row * KCB;
    float q = 0.f;
#pragma unroll
    for (int j = 0; j < 8; j++) {
        *reinterpret_cast<uint32_t*>(aq + (lane + j * 32) * 4) =
            pack4(q8(v[j].x, inv), q8(v[j].y, inv), q8(v[j].z, inv), q8(v[j].w, inv));
        if (uni) {
            const float4 w = reinterpret_cast<const float4*>(g_w2)[lane + j * 32];
            q += v[j].x * v[j].x * w.x + v[j].y * v[j].y * w.y
               + v[j].z * v[j].z * w.z + v[j].w * v[j].w * w.w;
        } else {
            float inv2 = inv / ALPHA;
            *reinterpret_cast<uint32_t*>(aq + FDIM + (lane + j * 32) * 4) =
                pack4(q8(v[j].x * v[j].x, inv2), q8(v[j].y * v[j].y, inv2),
                      q8(v[j].z * v[j].z, inv2), q8(v[j].w * v[j].w, inv2));
        }
    }
#pragma unroll
    for (int o = 16; o > 0; o >>= 1) q += __shfl_xor_sync(0xffffffffu, q, o);
    if (lane == 0) {
        g_q[row]  = q;
        g_sA[row] = absmax / 127.0f;
    }
}

// ---------------------------------------------------------------- stage loader
// A tile: 128 rows x 128B @ stage+0; B tile: 256 rows x 128B @ stage+16KB.
// 512 threads: 2 iters for A, 4 iters for B = 6 cp16/thread.
__device__ __forceinline__ void issue_stage(uint32_t smStage,
                                            const int8_t* gA, const int8_t* gB,
                                            int kByte, int tid) {
    const int8_t* a = gA + kByte;
    const int8_t* b = gB + kByte;
#pragma unroll
    for (int i = 0; i < 2; i++) {
        int id  = tid + i * NTHREADS;          // 0..1023  (A: 128 rows x 8 ch)
        int row = id >> 3, ch = id & 7;
        uint32_t dst = smStage + row * 128 + ((ch ^ (row & 7)) << 4);
        cp16(dst, a + (size_t)row * KCB + ch * 16);
    }
#pragma unroll
    for (int i = 0; i < 4; i++) {
        int id  = tid + i * NTHREADS;          // 0..2047  (B: 256 rows x 8 ch)
        int row = id >> 3, ch = id & 7;
        uint32_t dst = smStage + 16384 + row * 128 + ((ch ^ (row & 7)) << 4);
        cp16(dst, b + (size_t)row * KCB + ch * 16);
    }
    CP_COMMIT();
}

// ---------------------------------------------------------------- main kernel
// Block 128x256, 16 warps in 4(M) x 4(N), warp tile 32x64 (round-5 shape).
__global__ __launch_bounds__(NTHREADS, 1)
void gmm_main(float* __restrict__ out) {
    extern __shared__ char smem[];
    uint32_t sb = smem_u32(smem);
    float* sBias = reinterpret_cast<float*>(smem + SM_BIAS_OFF);
    float* sSw   = reinterpret_cast<float*>(smem + SM_SW_OFF);

    int tid  = threadIdx.x;
    int wid  = tid >> 5, lane = tid & 31;
    int wm   = wid & 3;          // 4 warps over M -> 32 rows each
    int wn   = wid >> 2;         // 4 warps over N -> 64 cols each

    int rowBase = blockIdx.y * BM;
    int colBase = blockIdx.x * BN;
    int kIters  = (g_uniform != 0) ? 8 : 16;

    if (tid < BN) {
        sBias[tid] = g_bias[colBase + tid];
        sSw[tid]   = g_sW[colBase + tid];
    }

    const int8_t* gA = g_Aq + (size_t)rowBase * KCB;
    const int8_t* gB = g_Wq + (size_t)colBase * KCB;

    // prologue: 3 stages in flight
    issue_stage(sb + 0 * STAGE_BYTES, gA, gB, 0 * BKB, tid);
    issue_stage(sb + 1 * STAGE_BYTES, gA, gB, 1 * BKB, tid);
    issue_stage(sb + 2 * STAGE_BYTES, gA, gB, 2 * BKB, tid);

    int acc[2][8][4];
#pragma unroll
    for (int mt = 0; mt < 2; mt++)
#pragma unroll
        for (int nt = 0; nt < 8; nt++)
#pragma unroll
            for (int j = 0; j < 4; j++) acc[mt][nt][j] = 0;

    // per-lane swizzled base offsets (XOR-composable with ks<<5)
    int cHi = lane >> 4;
    uint32_t offA[2], offB[4];
#pragma unroll
    for (int mt = 0; mt < 2; mt++) {
        int r = wm * 32 + (lane & 15) + mt * 16;
        offA[mt] = (uint32_t)(r * 128) + (uint32_t)(((cHi ^ (r & 7))) << 4);
    }
#pragma unroll
    for (int p = 0; p < 4; p++) {
        int r = wn * 64 + (lane & 15) + p * 16;
        offB[p] = (uint32_t)(16384 + r * 128) + (uint32_t)(((cHi ^ (r & 7))) << 4);
    }

#pragma unroll 1
    for (int s = 0; s < kIters; s++) {
        if (s + 2 < kIters)      CP_WAIT(2);
        else if (s + 1 < kIters) CP_WAIT(1);
        else                     CP_WAIT(0);
        __syncthreads();

        uint32_t smStage = sb + (uint32_t)(s & 3) * STAGE_BYTES;

        if (s + 3 < kIters)
            issue_stage(sb + (uint32_t)((s + 3) & 3) * STAGE_BYTES, gA, gB, (s + 3) * BKB, tid);

        uint32_t bA0 = smStage + offA[0], bA1 = smStage + offA[1];
        uint32_t bB0 = smStage + offB[0], bB1 = smStage + offB[1];
        uint32_t bB2 = smStage + offB[2], bB3 = smStage + offB[3];

#pragma unroll
        for (int ks = 0; ks < 4; ks++) {       // each ks = 32 int8 k-elems
            uint32_t kx = (uint32_t)ks << 5;
            uint32_t a[2][4], b[4][4];
            LDSM4(a[0], bA0 ^ kx);
            LDSM4(a[1], bA1 ^ kx);
            LDSM4(b[0], bB0 ^ kx);
            LDSM4(b[1], bB1 ^ kx);
            LDSM4(b[2], bB2 ^ kx);
            LDSM4(b[3], bB3 ^ kx);
#pragma unroll
            for (int mt = 0; mt < 2; mt++)
#pragma unroll
                for (int nt = 0; nt < 8; nt++) {
                    int p = nt >> 1, q = nt & 1;
                    MMAI8(acc[mt][nt], a[mt], b[p][q], b[p][q + 2]);
                }
        }
    }
    __syncthreads();

    // ------------- epilogue: dequant + bias + logsumexp(8) + q[row]
    int colq = (lane & 3) * 2;
    int kBase = (colBase >> 3) + wn * 8;
#pragma unroll
    for (int mt = 0; mt < 2; mt++) {
#pragma unroll
        for (int h = 0; h < 2; h++) {
            int row = rowBase + wm * 32 + mt * 16 + h * 8 + (lane >> 2);
            float sxr = g_sA[row];
            float qr  = g_q[row];
#pragma unroll
            for (int nt = 0; nt < 8; nt++) {
                int c0 = wn * 64 + nt * 8 + colq;
                float sc0 = sSw[c0] * sxr;
                float sc1 = sSw[c0 + 1] * sxr;
                float l0 = (float)acc[mt][nt][h * 2]     * sc0 + sBias[c0];
                float l1 = (float)acc[mt][nt][h * 2 + 1] * sc1 + sBias[c0 + 1];
                float m = fmaxf(l0, l1);
                m = fmaxf(m, __shfl_xor_sync(0xffffffffu, m, 1));
                m = fmaxf(m, __shfl_xor_sync(0xffffffffu, m, 2));
                float sum = fast_exp(l0 - m) + fast_exp(l1 - m);
                sum += __shfl_xor_sync(0xffffffffu, sum, 1);
                sum += __shfl_xor_sync(0xffffffffu, sum, 2);
                if ((lane & 3) == 0)
                    out[(size_t)row * NK + kBase + nt] = m + fast_log(sum) + qr;
            }
        }
    }
}

// ---------------------------------------------------------------- launch
extern "C" void kernel_launch(void* const* d_in, const int* in_sizes, int n_in,
                              void* d_out, int out_size) {
    const float* X       = (const float*)d_in[0];
    const float* mu      = (const float*)d_in[1];
    const float* log_cov = (const float*)d_in[2];
    const float* log_pi  = (const float*)d_in[3];
    float* out = (float*)d_out;

    cudaFuncSetAttribute(gmm_main, cudaFuncAttributeMaxDynamicSharedMemorySize, SMEM_TOTAL);

    initFlagW2<<<FDIM / 256, 256>>>(log_cov);
    checkUni<<<KLD - 1, 256>>>(log_cov);
    prepW<<<KLD, 256>>>(mu, log_cov);
    prepA<<<BTD / 8, 256>>>(X);
    prepPi<<<1, 256>>>(log_pi);

    dim3 grid(KLD / BN, BTD / BM);   // (8, 256)
    gmm_main<<<grid, NTHREADS, SMEM_TOTAL>>>(out);
}

// round 8
// speedup vs baseline: 1.3750x; 1.1440x over previous
#include <cuda_runtime.h>
#include <cuda_bf16.h>
#include <math.h>
#include <stdint.h>

// ---------------------------------------------------------------- problem dims
#define FDIM 1024
#define NK   256
#define NL   8
#define KLD  2048            // NK*NL
#define BTD  32768           // B*T

// Quantized operands live in a stage-major, pre-swizzled tiled layout:
//   tile t = row/128, stage s = kByte/128, r = row%128, chunk ch = 0..7
//   byte offset = ((t*16 + s)*128 + r)*128 + ((ch ^ (r&7))<<4) + within
// so each (tile, stage) block is one contiguous 16KB span == the exact smem
// image the ldmatrix swizzle expects. Bulk-copy friendly.

// ---------------------------------------------------------------- GEMM tiling
#define BM 128
#define BN 128
#define NTHREADS 256         // 8 warps: 4(M) x 2(N), warp tile 32x64 (R5 shape)
#define STAGES 3
#define STAGE_BYTES 32768                 // A 16KB + B 16KB
#define SM_BIAS_OFF (STAGES * STAGE_BYTES)          // 98304
#define SM_SW_OFF   (SM_BIAS_OFF + BN * 4)
#define SM_MBAR_OFF (SM_SW_OFF + BN * 4)            // 3 x 8B
#define SMEM_TOTAL  (SM_MBAR_OFF + 64)

#define ALPHA 8.0f           // scale equalizer for the x^2 half (fallback path)

// ---------------------------------------------------------------- device scratch
__device__ int8_t g_Aq[(size_t)BTD * 2048];   // 64 MB, tiled layout (16 stages/tile)
__device__ int8_t g_Wq[(size_t)KLD * 2048];   // 4 MB, tiled layout
__device__ float  g_bias[KLD];
__device__ float  g_sW[KLD];
__device__ float  g_sA[BTD];
__device__ float  g_w2[FDIM];
__device__ float  g_q[BTD];
__device__ int    g_uniform;

// ---------------------------------------------------------------- asm helpers
__device__ __forceinline__ uint32_t smem_u32(const void* p) {
    uint32_t a;
    asm("{ .reg .u64 t; cvta.to.shared.u64 t, %1; cvt.u32.u64 %0, t; }" : "=r"(a) : "l"(p));
    return a;
}
#define MBAR_INIT(a, c) asm volatile("mbarrier.init.shared.b64 [%0], %1;" :: "r"(a), "r"(c) : "memory")
#define MBAR_EXPECT_TX(a, b) \
    asm volatile("mbarrier.arrive.expect_tx.shared.b64 _, [%0], %1;" :: "r"(a), "r"(b) : "memory")
#define MBAR_WAIT(a, ph) do {                                                       \
    asm volatile("{\n\t.reg .pred P;\n\t"                                           \
        "W%=:\n\t"                                                                  \
        "mbarrier.try_wait.parity.shared.b64 P, [%0], %1, 0x989680;\n\t"            \
        "@P bra.uni D%=;\n\t"                                                       \
        "bra.uni W%=;\n\t"                                                          \
        "D%=:\n\t}" :: "r"(a), "r"(ph) : "memory");                                 \
} while (0)
#define BULK_G2S(dst, src, size, mbar)                                              \
    asm volatile("cp.async.bulk.shared::cta.global.mbarrier::complete_tx::bytes "   \
        "[%0], [%1], %2, [%3];" :: "r"(dst), "l"(src), "r"(size), "r"(mbar) : "memory")

#define LDSM4(r, addr)                                                           \
    asm volatile("ldmatrix.sync.aligned.m8n8.x4.shared.b16 {%0,%1,%2,%3}, [%4];" \
        : "=r"((r)[0]), "=r"((r)[1]), "=r"((r)[2]), "=r"((r)[3]) : "r"(addr))

#define MMAI8(c, a, b0, b1)                                                      \
    asm volatile("mma.sync.aligned.m16n8k32.row.col.s32.s8.s8.s32 "              \
        "{%0,%1,%2,%3}, {%4,%5,%6,%7}, {%8,%9}, {%0,%1,%2,%3};"                  \
        : "+r"((c)[0]), "+r"((c)[1]), "+r"((c)[2]), "+r"((c)[3])                 \
        : "r"((a)[0]), "r"((a)[1]), "r"((a)[2]), "r"((a)[3]), "r"(b0), "r"(b1))

// ---------------------------------------------------------------- fast math
__device__ __forceinline__ float fast_exp(float u) {   // e^u, u <= 0
    u = fmaxf(u, -60.0f);
    float z  = u * 1.4426950408889634f;
    float nf = rintf(z);
    float w  = fmaf(nf, -0.6931471805599453f, u);
    float p  = fmaf(w, 0.041666668f, 0.16666667f);
    p = fmaf(w, p, 0.5f);
    p = fmaf(w, p, 1.0f);
    p = fmaf(w, p, 1.0f);
    return p * __int_as_float(((int)nf + 127) << 23);
}
__device__ __forceinline__ float fast_log(float s) {   // ln(s), s in [1, 16]
    int ib = __float_as_int(s);
    int e  = (ib - 0x3f3504f3) >> 23;
    float m = __int_as_float(ib - (e << 23));
    float t = m - 1.0f;
    float p = -0.125f;
    p = fmaf(p, t, 0.14285714f);
    p = fmaf(p, t, -0.16666667f);
    p = fmaf(p, t, 0.2f);
    p = fmaf(p, t, -0.25f);
    p = fmaf(p, t, 0.33333333f);
    p = fmaf(p, t, -0.5f);
    p = fmaf(p, t, 1.0f);
    p = p * t;
    return fmaf((float)e, 0.6931471805599453f, p);
}

__device__ __forceinline__ int8_t q8(float v, float inv) {
    int q = __float2int_rn(v * inv);
    q = max(-127, min(127, q));
    return (int8_t)q;
}
__device__ __forceinline__ uint32_t pack4(int8_t a, int8_t b, int8_t c, int8_t d) {
    return (uint32_t)(uint8_t)a | ((uint32_t)(uint8_t)b << 8) |
           ((uint32_t)(uint8_t)c << 16) | ((uint32_t)(uint8_t)d << 24);
}

// tiled+swizzled byte offset for 4B store: row (global), idx = uint32 index
// within a 1024-elem half, half = 0 (x) or 1 (x^2); tiles of 128 rows.
__device__ __forceinline__ size_t tiled_off(int row, int idx, int half) {
    int t  = row >> 7, r = row & 127;
    int s  = (idx >> 5) + half * 8;
    int ch = (idx >> 2) & 7;
    int b  = (idx & 3) * 4;
    return ((size_t)(t * 16 + s) * 128 + r) * 128 + ((ch ^ (r & 7)) << 4) + b;
}

// ---------------------------------------------------------------- prep kernels
__global__ void initFlagW2(const float* __restrict__ log_cov) {
    int f = blockIdx.x * blockDim.x + threadIdx.x;
    if (f == 0) g_uniform = 1;
    g_w2[f] = -0.5f * expf(-log_cov[f]);
}

__global__ void checkUni(const float* __restrict__ log_cov) {
    int kl = blockIdx.x + 1, t = threadIdx.x;
    const uint4* a = reinterpret_cast<const uint4*>(log_cov + (size_t)kl * FDIM);
    const uint4* b = reinterpret_cast<const uint4*>(log_cov);
    uint4 x = a[t], y = b[t];
    bool ok = (x.x == y.x) && (x.y == y.y) && (x.z == y.z) && (x.w == y.w);
    if (!__syncthreads_and(ok)) {
        if (t == 0) atomicAnd(&g_uniform, 0);
    }
}

__global__ void prepW(const float* __restrict__ mu, const float* __restrict__ log_cov) {
    int kl = blockIdx.x, t = threadIdx.x;
    bool uni = (g_uniform != 0);
    const float* mu_r = mu + (size_t)kl * FDIM;
    const float* lc_r = log_cov + (size_t)kl * FDIM;

    float w[4], w2[4];
    float s_lc = 0.f, s_m2 = 0.f, am = 0.f;
#pragma unroll
    for (int j = 0; j < 4; j++) {
        int f = t * 4 + j;
        float lc = lc_r[f];
        float iv = expf(-lc);
        float m  = mu_r[f];
        w[j]  = m * iv;
        w2[j] = -0.5f * iv;
        s_lc += lc;
        s_m2 += m * m * iv;
        am = fmaxf(am, fabsf(w[j]));
    }
    __shared__ float sh0[256], sh1[256], shm[256];
    sh0[t] = s_lc; sh1[t] = s_m2; shm[t] = am;
    __syncthreads();
    for (int s = 128; s > 0; s >>= 1) {
        if (t < s) {
            sh0[t] += sh0[t + s];
            sh1[t] += sh1[t + s];
            shm[t] = fmaxf(shm[t], shm[t + s]);
        }
        __syncthreads();
    }
    float absmax = fmaxf(shm[0], 1e-20f);
    float inv = 127.0f / absmax;
    *reinterpret_cast<uint32_t*>(g_Wq + tiled_off(kl, t, 0)) =
        pack4(q8(w[0], inv), q8(w[1], inv), q8(w[2], inv), q8(w[3], inv));
    if (!uni) {
        float inv2 = inv * ALPHA;
        *reinterpret_cast<uint32_t*>(g_Wq + tiled_off(kl, t, 1)) =
            pack4(q8(w2[0], inv2), q8(w2[1], inv2), q8(w2[2], inv2), q8(w2[3], inv2));
    }
    if (t == 0) {
        g_sW[kl] = absmax / 127.0f;
        g_bias[kl] = -0.5f * (float)FDIM * 1.8378770664093453f - 0.5f * sh0[0] - 0.5f * sh1[0];
    }
}

__global__ void prepPi(const float* __restrict__ log_pi) {
    int k = blockIdx.x * blockDim.x + threadIdx.x;
    if (k >= NK) return;
    float v[NL], mx = -INFINITY;
#pragma unroll
    for (int l = 0; l < NL; l++) { v[l] = log_pi[k * NL + l]; mx = fmaxf(mx, v[l]); }
    float s = 0.f;
#pragma unroll
    for (int l = 0; l < NL; l++) s += expf(v[l] - mx);
    float lse = mx + logf(s);
#pragma unroll
    for (int l = 0; l < NL; l++) g_bias[k * NL + l] += v[l] - lse;
}

// warp-per-row: absmax -> quantize X (+ X^2 if fallback), q[row], scale.
__global__ void prepA(const float* __restrict__ X) {
    int lane = threadIdx.x & 31;
    int row  = blockIdx.x * 8 + (threadIdx.x >> 5);
    bool uni = (g_uniform != 0);

    const float4* xr = reinterpret_cast<const float4*>(X) + (size_t)row * 256;
    float4 v[8];
    float am = 0.f;
#pragma unroll
    for (int j = 0; j < 8; j++) {
        v[j] = xr[lane + j * 32];
        am = fmaxf(am, fmaxf(fmaxf(fabsf(v[j].x), fabsf(v[j].y)),
                             fmaxf(fabsf(v[j].z), fabsf(v[j].w))));
    }
#pragma unroll
    for (int o = 16; o > 0; o >>= 1) am = fmaxf(am, __shfl_xor_sync(0xffffffffu, am, o));
    float absmax = fmaxf(am, 1e-20f);
    float inv = 127.0f / absmax;

    float q = 0.f;
#pragma unroll
    for (int j = 0; j < 8; j++) {
        int idx = lane + j * 32;
        *reinterpret_cast<uint32_t*>(g_Aq + tiled_off(row, idx, 0)) =
            pack4(q8(v[j].x, inv), q8(v[j].y, inv), q8(v[j].z, inv), q8(v[j].w, inv));
        if (uni) {
            const float4 w = reinterpret_cast<const float4*>(g_w2)[idx];
            q += v[j].x * v[j].x * w.x + v[j].y * v[j].y * w.y
               + v[j].z * v[j].z * w.z + v[j].w * v[j].w * w.w;
        } else {
            float inv2 = inv / ALPHA;
            *reinterpret_cast<uint32_t*>(g_Aq + tiled_off(row, idx, 1)) =
                pack4(q8(v[j].x * v[j].x, inv2), q8(v[j].y * v[j].y, inv2),
                      q8(v[j].z * v[j].z, inv2), q8(v[j].w * v[j].w, inv2));
        }
    }
#pragma unroll
    for (int o = 16; o > 0; o >>= 1) q += __shfl_xor_sync(0xffffffffu, q, o);
    if (lane == 0) {
        g_q[row]  = q;
        g_sA[row] = absmax / 127.0f;
    }
}

// ---------------------------------------------------------------- main kernel
// Block 128x128, 8 warps in 4(M) x 2(N), warp tile 32x64; bulk-copy producer.
__global__ __launch_bounds__(NTHREADS, 2)
void gmm_main(float* __restrict__ out) {
    extern __shared__ char smem[];
    uint32_t sb = smem_u32(smem);
    float* sBias = reinterpret_cast<float*>(smem + SM_BIAS_OFF);
    float* sSw   = reinterpret_cast<float*>(smem + SM_SW_OFF);

    int tid  = threadIdx.x;
    int wid  = tid >> 5, lane = tid & 31;
    int wm   = wid & 3;          // 4 warps over M -> 32 rows each
    int wn   = wid >> 2;         // 2 warps over N -> 64 cols each

    int rowBase = blockIdx.y * BM;
    int colBase = blockIdx.x * BN;
    int kIters  = (g_uniform != 0) ? 8 : 16;

    const int8_t* gA = g_Aq + (size_t)blockIdx.y * (16 * 16384);
    const int8_t* gB = g_Wq + (size_t)blockIdx.x * (16 * 16384);

    uint32_t mb0 = sb + SM_MBAR_OFF, mb1 = mb0 + 8, mb2 = mb0 + 16;
    if (tid == 0) {
        MBAR_INIT(mb0, 1);
        MBAR_INIT(mb1, 1);
        MBAR_INIT(mb2, 1);
    }
    if (tid < BN) {
        sBias[tid] = g_bias[colBase + tid];
        sSw[tid]   = g_sW[colBase + tid];
    }
    __syncthreads();

    // prologue: 3 stages in flight (each stage = A 16KB + B 16KB)
    if (tid == 0) {
#pragma unroll
        for (int s = 0; s < 3; s++) {
            uint32_t mb = mb0 + s * 8;
            uint32_t dst = sb + s * STAGE_BYTES;
            MBAR_EXPECT_TX(mb, STAGE_BYTES);
            BULK_G2S(dst,         gA + (size_t)s * 16384, 16384, mb);
            BULK_G2S(dst + 16384, gB + (size_t)s * 16384, 16384, mb);
        }
    }

    int acc[2][8][4];
#pragma unroll
    for (int mt = 0; mt < 2; mt++)
#pragma unroll
        for (int nt = 0; nt < 8; nt++)
#pragma unroll
            for (int j = 0; j < 4; j++) acc[mt][nt][j] = 0;

    // per-lane swizzled base offsets (XOR-composable with ks<<5)
    int cHi = lane >> 4;
    uint32_t offA[2], offB[4];
#pragma unroll
    for (int mt = 0; mt < 2; mt++) {
        int r = wm * 32 + (lane & 15) + mt * 16;
        offA[mt] = (uint32_t)(r * 128) + (uint32_t)(((cHi ^ (r & 7))) << 4);
    }
#pragma unroll
    for (int p = 0; p < 4; p++) {
        int r = wn * 64 + (lane & 15) + p * 16;
        offB[p] = (uint32_t)(16384 + r * 128) + (uint32_t)(((cHi ^ (r & 7))) << 4);
    }

    int ph0 = 0, ph1 = 0, ph2 = 0;

#pragma unroll 1
    for (int s = 0; s < kIters; s++) {
        int b = s % 3;
        if (b == 0)      { MBAR_WAIT(mb0, ph0); ph0 ^= 1; }
        else if (b == 1) { MBAR_WAIT(mb1, ph1); ph1 ^= 1; }
        else             { MBAR_WAIT(mb2, ph2); ph2 ^= 1; }

        uint32_t smStage = sb + (uint32_t)b * STAGE_BYTES;
        uint32_t bA0 = smStage + offA[0], bA1 = smStage + offA[1];
        uint32_t bB0 = smStage + offB[0], bB1 = smStage + offB[1];
        uint32_t bB2 = smStage + offB[2], bB3 = smStage + offB[3];

#pragma unroll
        for (int ks = 0; ks < 4; ks++) {       // each ks = 32 int8 k-elems
            uint32_t kx = (uint32_t)ks << 5;
            uint32_t a[2][4], bb[4][4];
            LDSM4(a[0], bA0 ^ kx);
            LDSM4(a[1], bA1 ^ kx);
            LDSM4(bb[0], bB0 ^ kx);
            LDSM4(bb[1], bB1 ^ kx);
            LDSM4(bb[2], bB2 ^ kx);
            LDSM4(bb[3], bB3 ^ kx);
#pragma unroll
            for (int mt = 0; mt < 2; mt++)
#pragma unroll
                for (int nt = 0; nt < 8; nt++) {
                    int p = nt >> 1, q = nt & 1;
                    MMAI8(acc[mt][nt], a[mt], bb[p][q], bb[p][q + 2]);
                }
        }

        // all warps done reading buffer b -> refill it with stage s+3
        __syncthreads();
        if (tid == 0 && s + 3 < kIters) {
            uint32_t mb = mb0 + b * 8;
            uint32_t dst = sb + (uint32_t)b * STAGE_BYTES;
            MBAR_EXPECT_TX(mb, STAGE_BYTES);
            BULK_G2S(dst,         gA + (size_t)(s + 3) * 16384, 16384, mb);
            BULK_G2S(dst + 16384, gB + (size_t)(s + 3) * 16384, 16384, mb);
        }
    }

    // ------------- epilogue: dequant + bias + logsumexp(8) + q[row]
    int colq = (lane & 3) * 2;
    int kBase = (colBase >> 3) + wn * 8;
#pragma unroll
    for (int mt = 0; mt < 2; mt++) {
#pragma unroll
        for (int h = 0; h < 2; h++) {
            int row = rowBase + wm * 32 + mt * 16 + h * 8 + (lane >> 2);
            float sxr = g_sA[row];
            float qr  = g_q[row];
#pragma unroll
            for (int nt = 0; nt < 8; nt++) {
                int c0 = wn * 64 + nt * 8 + colq;
                float sc0 = sSw[c0] * sxr;
                float sc1 = sSw[c0 + 1] * sxr;
                float l0 = (float)acc[mt][nt][h * 2]     * sc0 + sBias[c0];
                float l1 = (float)acc[mt][nt][h * 2 + 1] * sc1 + sBias[c0 + 1];
                float m = fmaxf(l0, l1);
                m = fmaxf(m, __shfl_xor_sync(0xffffffffu, m, 1));
                m = fmaxf(m, __shfl_xor_sync(0xffffffffu, m, 2));
                float sum = fast_exp(l0 - m) + fast_exp(l1 - m);
                sum += __shfl_xor_sync(0xffffffffu, sum, 1);
                sum += __shfl_xor_sync(0xffffffffu, sum, 2);
                if ((lane & 3) == 0)
                    out[(size_t)row * NK + kBase + nt] = m + fast_log(sum) + qr;
            }
        }
    }
}

// ---------------------------------------------------------------- launch
extern "C" void kernel_launch(void* const* d_in, const int* in_sizes, int n_in,
                              void* d_out, int out_size) {
    const float* X       = (const float*)d_in[0];
    const float* mu      = (const float*)d_in[1];
    const float* log_cov = (const float*)d_in[2];
    const float* log_pi  = (const float*)d_in[3];
    float* out = (float*)d_out;

    cudaFuncSetAttribute(gmm_main, cudaFuncAttributeMaxDynamicSharedMemorySize, SMEM_TOTAL);

    initFlagW2<<<FDIM / 256, 256>>>(log_cov);
    checkUni<<<KLD - 1, 256>>>(log_cov);
    prepW<<<KLD, 256>>>(mu, log_cov);
    prepA<<<BTD / 8, 256>>>(X);
    prepPi<<<1, 256>>>(log_pi);

    dim3 grid(KLD / BN, BTD / BM);   // (16, 256)
    gmm_main<<<grid, NTHREADS, SMEM_TOTAL>>>(out);
}

// round 9
// speedup vs baseline: 1.4395x; 1.0469x over previous
#include <cuda_runtime.h>
#include <cuda_bf16.h>
#include <math.h>
#include <stdint.h>

// ---------------------------------------------------------------- problem dims
#define FDIM 1024
#define NK   256
#define NL   8
#define KLD  2048            // NK*NL
#define BTD  32768           // B*T

// Quantized operands live in a stage-major, pre-swizzled tiled layout:
//   tile t = row/128, stage s = kByte/128, r = row%128, chunk ch = 0..7
//   byte offset = ((t*16 + s)*128 + r)*128 + ((ch ^ (r&7))<<4) + within
// Each (tile, stage) block is one contiguous 16KB span == the exact smem
// image the ldmatrix swizzle expects. Bulk-copy friendly.

// ---------------------------------------------------------------- GEMM tiling
#define BM 128
#define BN 128
#define NTHREADS 256         // 8 warps: 4(M) x 2(N), warp tile 32x64
#define STAGES 3
#define STAGE_BYTES 32768                 // A 16KB + B 16KB
#define SM_BIAS_OFF (STAGES * STAGE_BYTES)          // 98304
#define SM_SW_OFF   (SM_BIAS_OFF + BN * 4)
#define SM_MBAR_OFF (SM_SW_OFF + BN * 4)            // 3 full + 3 empty x 8B
#define SMEM_TOTAL  (SM_MBAR_OFF + 64)

#define ALPHA 8.0f           // scale equalizer for the x^2 half (fallback path)

// ---------------------------------------------------------------- device scratch
__device__ int8_t g_Aq[(size_t)BTD * 2048];   // 64 MB, tiled layout (16 stages/tile)
__device__ int8_t g_Wq[(size_t)KLD * 2048];   // 4 MB, tiled layout
__device__ float  g_bias[KLD];
__device__ float  g_sW[KLD];
__device__ float  g_sA[BTD];
__device__ float  g_w2[FDIM];
__device__ float  g_q[BTD];
__device__ int    g_uniform = 1;   // atomicAnd-only; data-fixed -> deterministic

// ---------------------------------------------------------------- asm helpers
__device__ __forceinline__ uint32_t smem_u32(const void* p) {
    uint32_t a;
    asm("{ .reg .u64 t; cvta.to.shared.u64 t, %1; cvt.u32.u64 %0, t; }" : "=r"(a) : "l"(p));
    return a;
}
#define MBAR_INIT(a, c) asm volatile("mbarrier.init.shared.b64 [%0], %1;" :: "r"(a), "r"(c) : "memory")
#define MBAR_ARRIVE(a)  asm volatile("mbarrier.arrive.shared.b64 _, [%0];" :: "r"(a) : "memory")
#define MBAR_EXPECT_TX(a, b) \
    asm volatile("mbarrier.arrive.expect_tx.shared.b64 _, [%0], %1;" :: "r"(a), "r"(b) : "memory")
#define MBAR_WAIT(a, ph) do {                                                       \
    asm volatile("{\n\t.reg .pred P;\n\t"                                           \
        "W%=:\n\t"                                                                  \
        "mbarrier.try_wait.parity.shared.b64 P, [%0], %1, 0x989680;\n\t"            \
        "@P bra.uni D%=;\n\t"                                                       \
        "bra.uni W%=;\n\t"                                                          \
        "D%=:\n\t}" :: "r"(a), "r"(ph) : "memory");                                 \
} while (0)
#define BULK_G2S(dst, src, size, mbar)                                              \
    asm volatile("cp.async.bulk.shared::cta.global.mbarrier::complete_tx::bytes "   \
        "[%0], [%1], %2, [%3];" :: "r"(dst), "l"(src), "r"(size), "r"(mbar) : "memory")

#define LDSM4(r, addr)                                                           \
    asm volatile("ldmatrix.sync.aligned.m8n8.x4.shared.b16 {%0,%1,%2,%3}, [%4];" \
        : "=r"((r)[0]), "=r"((r)[1]), "=r"((r)[2]), "=r"((r)[3]) : "r"(addr))

#define MMAI8(c, a, b0, b1)                                                      \
    asm volatile("mma.sync.aligned.m16n8k32.row.col.s32.s8.s8.s32 "              \
        "{%0,%1,%2,%3}, {%4,%5,%6,%7}, {%8,%9}, {%0,%1,%2,%3};"                  \
        : "+r"((c)[0]), "+r"((c)[1]), "+r"((c)[2]), "+r"((c)[3])                 \
        : "r"((a)[0]), "r"((a)[1]), "r"((a)[2]), "r"((a)[3]), "r"(b0), "r"(b1))

// ---------------------------------------------------------------- fast math
__device__ __forceinline__ float fast_exp(float u) {   // e^u, u <= 0
    u = fmaxf(u, -60.0f);
    float z  = u * 1.4426950408889634f;
    float nf = rintf(z);
    float w  = fmaf(nf, -0.6931471805599453f, u);
    float p  = fmaf(w, 0.041666668f, 0.16666667f);
    p = fmaf(w, p, 0.5f);
    p = fmaf(w, p, 1.0f);
    p = fmaf(w, p, 1.0f);
    return p * __int_as_float(((int)nf + 127) << 23);
}
__device__ __forceinline__ float fast_log(float s) {   // ln(s), s in [1, 16]
    int ib = __float_as_int(s);
    int e  = (ib - 0x3f3504f3) >> 23;
    float m = __int_as_float(ib - (e << 23));
    float t = m - 1.0f;
    float p = -0.125f;
    p = fmaf(p, t, 0.14285714f);
    p = fmaf(p, t, -0.16666667f);
    p = fmaf(p, t, 0.2f);
    p = fmaf(p, t, -0.25f);
    p = fmaf(p, t, 0.33333333f);
    p = fmaf(p, t, -0.5f);
    p = fmaf(p, t, 1.0f);
    p = p * t;
    return fmaf((float)e, 0.6931471805599453f, p);
}

__device__ __forceinline__ int8_t q8(float v, float inv) {
    int q = __float2int_rn(v * inv);
    q = max(-127, min(127, q));
    return (int8_t)q;
}
__device__ __forceinline__ uint32_t pack4(int8_t a, int8_t b, int8_t c, int8_t d) {
    return (uint32_t)(uint8_t)a | ((uint32_t)(uint8_t)b << 8) |
           ((uint32_t)(uint8_t)c << 16) | ((uint32_t)(uint8_t)d << 24);
}

// tiled+swizzled byte offset for a 4B store
__device__ __forceinline__ size_t tiled_off(int row, int idx, int half) {
    int t  = row >> 7, r = row & 127;
    int s  = (idx >> 5) + half * 8;
    int ch = (idx >> 2) & 7;
    int b  = (idx & 3) * 4;
    return ((size_t)(t * 16 + s) * 128 + r) * 128 + ((ch ^ (r & 7)) << 4) + b;
}

// ---------------------------------------------------------------- prep kernels
// prep0: all blocks uni-check; block 0 writes g_w2; block 1 seeds g_bias with
// log_softmax(log_pi) (prepW then adds the Gaussian normalizer terms).
__global__ void prep0(const float* __restrict__ log_cov,
                      const float* __restrict__ log_pi) {
    int kl = blockIdx.x, t = threadIdx.x;
    if (kl > 0) {
        const uint4* a = reinterpret_cast<const uint4*>(log_cov + (size_t)kl * FDIM);
        const uint4* b = reinterpret_cast<const uint4*>(log_cov);
        uint4 x = a[t], y = b[t];
        bool ok = (x.x == y.x) && (x.y == y.y) && (x.z == y.z) && (x.w == y.w);
        if (!__syncthreads_and(ok)) {
            if (t == 0) atomicAnd(&g_uniform, 0);
        }
    }
    if (kl == 0) {
#pragma unroll
        for (int j = 0; j < 4; j++) {
            int f = t * 4 + j;
            g_w2[f] = -0.5f * expf(-log_cov[f]);
        }
    }
    if (kl == 1) {
        int k = t;                         // 256 threads == NK
        float v[NL], mx = -INFINITY;
#pragma unroll
        for (int l = 0; l < NL; l++) { v[l] = log_pi[k * NL + l]; mx = fmaxf(mx, v[l]); }
        float s = 0.f;
#pragma unroll
        for (int l = 0; l < NL; l++) s += expf(v[l] - mx);
        float lse = mx + logf(s);
#pragma unroll
        for (int l = 0; l < NL; l++) g_bias[k * NL + l] = v[l] - lse;
    }
}

// prepW: quantize w = mu*iv, always write w2 half, add normalizer to bias.
__global__ void prepW(const float* __restrict__ mu, const float* __restrict__ log_cov) {
    int kl = blockIdx.x, t = threadIdx.x;
    const float* mu_r = mu + (size_t)kl * FDIM;
    const float* lc_r = log_cov + (size_t)kl * FDIM;

    float w[4], w2[4];
    float s_lc = 0.f, s_m2 = 0.f, am = 0.f;
#pragma unroll
    for (int j = 0; j < 4; j++) {
        int f = t * 4 + j;
        float lc = lc_r[f];
        float iv = expf(-lc);
        float m  = mu_r[f];
        w[j]  = m * iv;
        w2[j] = -0.5f * iv;
        s_lc += lc;
        s_m2 += m * m * iv;
        am = fmaxf(am, fabsf(w[j]));
    }
    __shared__ float sh0[256], sh1[256], shm[256];
    sh0[t] = s_lc; sh1[t] = s_m2; shm[t] = am;
    __syncthreads();
    for (int s = 128; s > 0; s >>= 1) {
        if (t < s) {
            sh0[t] += sh0[t + s];
            sh1[t] += sh1[t + s];
            shm[t] = fmaxf(shm[t], shm[t + s]);
        }
        __syncthreads();
    }
    float absmax = fmaxf(shm[0], 1e-20f);
    float inv = 127.0f / absmax;
    *reinterpret_cast<uint32_t*>(g_Wq + tiled_off(kl, t, 0)) =
        pack4(q8(w[0], inv), q8(w[1], inv), q8(w[2], inv), q8(w[3], inv));
    float inv2 = inv * ALPHA;
    *reinterpret_cast<uint32_t*>(g_Wq + tiled_off(kl, t, 1)) =
        pack4(q8(w2[0], inv2), q8(w2[1], inv2), q8(w2[2], inv2), q8(w2[3], inv2));
    if (t == 0) {
        g_sW[kl] = absmax / 127.0f;
        g_bias[kl] += -0.5f * (float)FDIM * 1.8378770664093453f - 0.5f * sh0[0] - 0.5f * sh1[0];
    }
}

// warp-per-row: absmax -> quantize X (+ X^2 if fallback), q[row], scale.
__global__ void prepA(const float* __restrict__ X) {
    int lane = threadIdx.x & 31;
    int row  = blockIdx.x * 8 + (threadIdx.x >> 5);
    bool uni = (g_uniform != 0);

    const float4* xr = reinterpret_cast<const float4*>(X) + (size_t)row * 256;
    float4 v[8];
    float am = 0.f;
#pragma unroll
    for (int j = 0; j < 8; j++) {
        v[j] = xr[lane + j * 32];
        am = fmaxf(am, fmaxf(fmaxf(fabsf(v[j].x), fabsf(v[j].y)),
                             fmaxf(fabsf(v[j].z), fabsf(v[j].w))));
    }
#pragma unroll
    for (int o = 16; o > 0; o >>= 1) am = fmaxf(am, __shfl_xor_sync(0xffffffffu, am, o));
    float absmax = fmaxf(am, 1e-20f);
    float inv = 127.0f / absmax;

    float q = 0.f;
#pragma unroll
    for (int j = 0; j < 8; j++) {
        int idx = lane + j * 32;
        *reinterpret_cast<uint32_t*>(g_Aq + tiled_off(row, idx, 0)) =
            pack4(q8(v[j].x, inv), q8(v[j].y, inv), q8(v[j].z, inv), q8(v[j].w, inv));
        if (uni) {
            const float4 w = reinterpret_cast<const float4*>(g_w2)[idx];
            q += v[j].x * v[j].x * w.x + v[j].y * v[j].y * w.y
               + v[j].z * v[j].z * w.z + v[j].w * v[j].w * w.w;
        } else {
            float inv2 = inv / ALPHA;
            *reinterpret_cast<uint32_t*>(g_Aq + tiled_off(row, idx, 1)) =
                pack4(q8(v[j].x * v[j].x, inv2), q8(v[j].y * v[j].y, inv2),
                      q8(v[j].z * v[j].z, inv2), q8(v[j].w * v[j].w, inv2));
        }
    }
#pragma unroll
    for (int o = 16; o > 0; o >>= 1) q += __shfl_xor_sync(0xffffffffu, q, o);
    if (lane == 0) {
        g_q[row]  = q;
        g_sA[row] = absmax / 127.0f;
    }
}

// ---------------------------------------------------------------- main kernel
// Block 128x128, 8 warps 4(M)x2(N), warp tile 32x64; bulk-copy producer with
// per-buffer full/empty mbarriers (no mainloop __syncthreads).
__global__ __launch_bounds__(NTHREADS, 2)
void gmm_main(float* __restrict__ out) {
    extern __shared__ char smem[];
    uint32_t sb = smem_u32(smem);
    float* sBias = reinterpret_cast<float*>(smem + SM_BIAS_OFF);
    float* sSw   = reinterpret_cast<float*>(smem + SM_SW_OFF);

    int tid  = threadIdx.x;
    int wid  = tid >> 5, lane = tid & 31;
    int wm   = wid & 3;          // 4 warps over M -> 32 rows each
    int wn   = wid >> 2;         // 2 warps over N -> 64 cols each

    int rowBase = blockIdx.y * BM;
    int colBase = blockIdx.x * BN;
    int kIters  = (g_uniform != 0) ? 8 : 16;

    const int8_t* gA = g_Aq + (size_t)blockIdx.y * (16 * 16384);
    const int8_t* gB = g_Wq + (size_t)blockIdx.x * (16 * 16384);

    uint32_t mbF = sb + SM_MBAR_OFF;        // 3 full barriers
    uint32_t mbE = mbF + 24;                // 3 empty barriers
    if (tid == 0) {
#pragma unroll
        for (int s = 0; s < 3; s++) {
            MBAR_INIT(mbF + s * 8, 1);      // tx-based completion
            MBAR_INIT(mbE + s * 8, 8);      // one arrive per warp
        }
    }
    if (tid < BN) {
        sBias[tid] = g_bias[colBase + tid];
        sSw[tid]   = g_sW[colBase + tid];
    }
    __syncthreads();

    // prologue: 3 stages in flight
    if (tid == 0) {
#pragma unroll
        for (int s = 0; s < 3; s++) {
            uint32_t mb = mbF + s * 8;
            uint32_t dst = sb + s * STAGE_BYTES;
            MBAR_EXPECT_TX(mb, STAGE_BYTES);
            BULK_G2S(dst,         gA + (size_t)s * 16384, 16384, mb);
            BULK_G2S(dst + 16384, gB + (size_t)s * 16384, 16384, mb);
        }
    }

    int acc[2][8][4];
#pragma unroll
    for (int mt = 0; mt < 2; mt++)
#pragma unroll
        for (int nt = 0; nt < 8; nt++)
#pragma unroll
            for (int j = 0; j < 4; j++) acc[mt][nt][j] = 0;

    // per-lane swizzled base offsets (XOR-composable with ks<<5)
    int cHi = lane >> 4;
    uint32_t offA[2], offB[4];
#pragma unroll
    for (int mt = 0; mt < 2; mt++) {
        int r = wm * 32 + (lane & 15) + mt * 16;
        offA[mt] = (uint32_t)(r * 128) + (uint32_t)(((cHi ^ (r & 7))) << 4);
    }
#pragma unroll
    for (int p = 0; p < 4; p++) {
        int r = wn * 64 + (lane & 15) + p * 16;
        offB[p] = (uint32_t)(16384 + r * 128) + (uint32_t)(((cHi ^ (r & 7))) << 4);
    }

    int phF0 = 0, phF1 = 0, phF2 = 0;
    int phE0 = 0, phE1 = 0, phE2 = 0;

#pragma unroll 1
    for (int s = 0; s < kIters; s++) {
        int b = s % 3;
        uint32_t fb = mbF + (uint32_t)b * 8;
        uint32_t eb = mbE + (uint32_t)b * 8;
        if (b == 0)      { MBAR_WAIT(fb, phF0); phF0 ^= 1; }
        else if (b == 1) { MBAR_WAIT(fb, phF1); phF1 ^= 1; }
        else             { MBAR_WAIT(fb, phF2); phF2 ^= 1; }

        uint32_t smStage = sb + (uint32_t)b * STAGE_BYTES;
        uint32_t bA0 = smStage + offA[0], bA1 = smStage + offA[1];
        uint32_t bB0 = smStage + offB[0], bB1 = smStage + offB[1];
        uint32_t bB2 = smStage + offB[2], bB3 = smStage + offB[3];

#pragma unroll
        for (int ks = 0; ks < 4; ks++) {       // each ks = 32 int8 k-elems
            uint32_t kx = (uint32_t)ks << 5;
            uint32_t a[2][4], bb[4][4];
            LDSM4(a[0], bA0 ^ kx);
            LDSM4(a[1], bA1 ^ kx);
            LDSM4(bb[0], bB0 ^ kx);
            LDSM4(bb[1], bB1 ^ kx);
            LDSM4(bb[2], bB2 ^ kx);
            LDSM4(bb[3], bB3 ^ kx);
#pragma unroll
            for (int mt = 0; mt < 2; mt++)
#pragma unroll
                for (int nt = 0; nt < 8; nt++) {
                    int p = nt >> 1, q = nt & 1;
                    MMAI8(acc[mt][nt], a[mt], bb[p][q], bb[p][q + 2]);
                }
        }

        // this warp is done reading buffer b (release-arrive)
        if (lane == 0) MBAR_ARRIVE(eb);

        // producer: wait for all 8 warps, then refill buffer b with stage s+3
        if (tid == 0 && s + 3 < kIters) {
            if (b == 0)      { MBAR_WAIT(eb, phE0); phE0 ^= 1; }
            else if (b == 1) { MBAR_WAIT(eb, phE1); phE1 ^= 1; }
            else             { MBAR_WAIT(eb, phE2); phE2 ^= 1; }
            uint32_t dst = sb + (uint32_t)b * STAGE_BYTES;
            MBAR_EXPECT_TX(fb, STAGE_BYTES);
            BULK_G2S(dst,         gA + (size_t)(s + 3) * 16384, 16384, fb);
            BULK_G2S(dst + 16384, gB + (size_t)(s + 3) * 16384, 16384, fb);
        }
    }

    // ------------- epilogue: dequant + bias + logsumexp(8) + q[row]
    int colq = (lane & 3) * 2;
    int kBase = (colBase >> 3) + wn * 8;
#pragma unroll
    for (int mt = 0; mt < 2; mt++) {
#pragma unroll
        for (int h = 0; h < 2; h++) {
            int row = rowBase + wm * 32 + mt * 16 + h * 8 + (lane >> 2);
            float sxr = g_sA[row];
            float qr  = g_q[row];
#pragma unroll
            for (int nt = 0; nt < 8; nt++) {
                int c0 = wn * 64 + nt * 8 + colq;
                float sc0 = sSw[c0] * sxr;
                float sc1 = sSw[c0 + 1] * sxr;
                float l0 = (float)acc[mt][nt][h * 2]     * sc0 + sBias[c0];
                float l1 = (float)acc[mt][nt][h * 2 + 1] * sc1 + sBias[c0 + 1];
                float m = fmaxf(l0, l1);
                m = fmaxf(m, __shfl_xor_sync(0xffffffffu, m, 1));
                m = fmaxf(m, __shfl_xor_sync(0xffffffffu, m, 2));
                float sum = fast_exp(l0 - m) + fast_exp(l1 - m);
                sum += __shfl_xor_sync(0xffffffffu, sum, 1);
                sum += __shfl_xor_sync(0xffffffffu, sum, 2);
                if ((lane & 3) == 0)
                    out[(size_t)row * NK + kBase + nt] = m + fast_log(sum) + qr;
            }
        }
    }
}

// ---------------------------------------------------------------- launch
extern "C" void kernel_launch(void* const* d_in, const int* in_sizes, int n_in,
                              void* d_out, int out_size) {
    const float* X       = (const float*)d_in[0];
    const float* mu      = (const float*)d_in[1];
    const float* log_cov = (const float*)d_in[2];
    const float* log_pi  = (const float*)d_in[3];
    float* out = (float*)d_out;

    cudaFuncSetAttribute(gmm_main, cudaFuncAttributeMaxDynamicSharedMemorySize, SMEM_TOTAL);

    prep0<<<KLD, 256>>>(log_cov, log_pi);
    prepW<<<KLD, 256>>>(mu, log_cov);
    prepA<<<BTD / 8, 256>>>(X);

    dim3 grid(KLD / BN, BTD / BM);   // (16, 256)
    gmm_main<<<grid, NTHREADS, SMEM_TOTAL>>>(out);
}

// round 10
// speedup vs baseline: 1.6090x; 1.1178x over previous
#include <cuda_runtime.h>
#include <cuda_bf16.h>
#include <math.h>
#include <stdint.h>

// ---------------------------------------------------------------- problem dims
#define FDIM 1024
#define NK   256
#define NL   8
#define KLD  2048            // NK*NL
#define BTD  32768           // B*T

// Quantized operands live in a stage-major, pre-swizzled tiled layout:
//   tile t = row/128, stage s = kByte/128, r = row%128, chunk ch = 0..7
//   byte offset = ((t*16 + s)*128 + r)*128 + ((ch ^ (r&7))<<4) + within
// Each (tile, stage) block is one contiguous 16KB span == the exact smem
// image the ldmatrix swizzle expects. Bulk-copy friendly.

// ---------------------------------------------------------------- GEMM tiling
#define BM 128
#define BN 128
#define NTHREADS 256         // 8 warps: 4(M) x 2(N), warp tile 32x64
#define STAGES 3
#define STAGE_BYTES 32768                 // A 16KB + B 16KB
#define SM_BW_OFF   (STAGES * STAGE_BYTES)          // 98304: float2 (bias, sW) x 128
#define SM_MBAR_OFF (SM_BW_OFF + BN * 8)            // 3 full + 3 empty x 8B
#define SMEM_TOTAL  (SM_MBAR_OFF + 64)

#define EPITCH 136           // fp32 pitch of the epilogue logit tile (128x136 = 69.6KB)

#define ALPHA 8.0f           // scale equalizer for the x^2 half (fallback path)

// ---------------------------------------------------------------- device scratch
__device__ int8_t g_Aq[(size_t)BTD * 2048];   // 64 MB, tiled layout (16 stages/tile)
__device__ int8_t g_Wq[(size_t)KLD * 2048];   // 4 MB, tiled layout
__device__ float  g_bias[KLD];
__device__ float  g_sW[KLD];
__device__ float  g_sA[BTD];
__device__ float  g_w2[FDIM];
__device__ float  g_q[BTD];
__device__ int    g_uniform = 1;   // atomicAnd-only; data-fixed -> deterministic

// ---------------------------------------------------------------- asm helpers
__device__ __forceinline__ uint32_t smem_u32(const void* p) {
    uint32_t a;
    asm("{ .reg .u64 t; cvta.to.shared.u64 t, %1; cvt.u32.u64 %0, t; }" : "=r"(a) : "l"(p));
    return a;
}
#define MBAR_INIT(a, c) asm volatile("mbarrier.init.shared.b64 [%0], %1;" :: "r"(a), "r"(c) : "memory")
#define MBAR_ARRIVE(a)  asm volatile("mbarrier.arrive.shared.b64 _, [%0];" :: "r"(a) : "memory")
#define MBAR_EXPECT_TX(a, b) \
    asm volatile("mbarrier.arrive.expect_tx.shared.b64 _, [%0], %1;" :: "r"(a), "r"(b) : "memory")
#define MBAR_WAIT(a, ph) do {                                                       \
    asm volatile("{\n\t.reg .pred P;\n\t"                                           \
        "W%=:\n\t"                                                                  \
        "mbarrier.try_wait.parity.shared.b64 P, [%0], %1, 0x989680;\n\t"            \
        "@P bra.uni D%=;\n\t"                                                       \
        "bra.uni W%=;\n\t"                                                          \
        "D%=:\n\t}" :: "r"(a), "r"(ph) : "memory");                                 \
} while (0)
#define BULK_G2S(dst, src, size, mbar)                                              \
    asm volatile("cp.async.bulk.shared::cta.global.mbarrier::complete_tx::bytes "   \
        "[%0], [%1], %2, [%3];" :: "r"(dst), "l"(src), "r"(size), "r"(mbar) : "memory")

#define LDSM4(r, addr)                                                           \
    asm volatile("ldmatrix.sync.aligned.m8n8.x4.shared.b16 {%0,%1,%2,%3}, [%4];" \
        : "=r"((r)[0]), "=r"((r)[1]), "=r"((r)[2]), "=r"((r)[3]) : "r"(addr))

#define MMAI8(c, a, b0, b1)                                                      \
    asm volatile("mma.sync.aligned.m16n8k32.row.col.s32.s8.s8.s32 "              \
        "{%0,%1,%2,%3}, {%4,%5,%6,%7}, {%8,%9}, {%0,%1,%2,%3};"                  \
        : "+r"((c)[0]), "+r"((c)[1]), "+r"((c)[2]), "+r"((c)[3])                 \
        : "r"((a)[0]), "r"((a)[1]), "r"((a)[2]), "r"((a)[3]), "r"(b0), "r"(b1))

// ---------------------------------------------------------------- fast math
__device__ __forceinline__ float fast_exp(float u) {   // e^u, u <= 0
    u = fmaxf(u, -60.0f);
    float z  = u * 1.4426950408889634f;
    float nf = rintf(z);
    float w  = fmaf(nf, -0.6931471805599453f, u);      // |w| <= ln2/2
    float p  = fmaf(w, 0.16666667f, 0.5f);
    p = fmaf(w, p, 1.0f);
    p = fmaf(w, p, 1.0f);
    return p * __int_as_float(((int)nf + 127) << 23);
}
__device__ __forceinline__ float fast_log(float s) {   // ln(s), s in [1, 16]
    int ib = __float_as_int(s);
    int e  = (ib - 0x3f3504f3) >> 23;
    float m = __int_as_float(ib - (e << 23));
    float t = m - 1.0f;
    float p = -0.125f;
    p = fmaf(p, t, 0.14285714f);
    p = fmaf(p, t, -0.16666667f);
    p = fmaf(p, t, 0.2f);
    p = fmaf(p, t, -0.25f);
    p = fmaf(p, t, 0.33333333f);
    p = fmaf(p, t, -0.5f);
    p = fmaf(p, t, 1.0f);
    p = p * t;
    return fmaf((float)e, 0.6931471805599453f, p);
}

__device__ __forceinline__ int8_t q8(float v, float inv) {
    int q = __float2int_rn(v * inv);
    q = max(-127, min(127, q));
    return (int8_t)q;
}
__device__ __forceinline__ uint32_t pack4(int8_t a, int8_t b, int8_t c, int8_t d) {
    return (uint32_t)(uint8_t)a | ((uint32_t)(uint8_t)b << 8) |
           ((uint32_t)(uint8_t)c << 16) | ((uint32_t)(uint8_t)d << 24);
}

// tiled+swizzled byte offset for a 4B store
__device__ __forceinline__ size_t tiled_off(int row, int idx, int half) {
    int t  = row >> 7, r = row & 127;
    int s  = (idx >> 5) + half * 8;
    int ch = (idx >> 2) & 7;
    int b  = (idx & 3) * 4;
    return ((size_t)(t * 16 + s) * 128 + r) * 128 + ((ch ^ (r & 7)) << 4) + b;
}

// ---------------------------------------------------------------- prep kernels
// prep0: all blocks uni-check; block 0 writes g_w2; block 1 seeds g_bias with
// log_softmax(log_pi) (prepW then adds the Gaussian normalizer terms).
__global__ void prep0(const float* __restrict__ log_cov,
                      const float* __restrict__ log_pi) {
    int kl = blockIdx.x, t = threadIdx.x;
    if (kl > 0) {
        const uint4* a = reinterpret_cast<const uint4*>(log_cov + (size_t)kl * FDIM);
        const uint4* b = reinterpret_cast<const uint4*>(log_cov);
        uint4 x = a[t], y = b[t];
        bool ok = (x.x == y.x) && (x.y == y.y) && (x.z == y.z) && (x.w == y.w);
        if (!__syncthreads_and(ok)) {
            if (t == 0) atomicAnd(&g_uniform, 0);
        }
    }
    if (kl == 0) {
#pragma unroll
        for (int j = 0; j < 4; j++) {
            int f = t * 4 + j;
            g_w2[f] = -0.5f * expf(-log_cov[f]);
        }
    }
    if (kl == 1) {
        int k = t;                         // 256 threads == NK
        float v[NL], mx = -INFINITY;
#pragma unroll
        for (int l = 0; l < NL; l++) { v[l] = log_pi[k * NL + l]; mx = fmaxf(mx, v[l]); }
        float s = 0.f;
#pragma unroll
        for (int l = 0; l < NL; l++) s += expf(v[l] - mx);
        float lse = mx + logf(s);
#pragma unroll
        for (int l = 0; l < NL; l++) g_bias[k * NL + l] = v[l] - lse;
    }
}

// prepW: quantize w = mu*iv, always write w2 half, add normalizer to bias.
__global__ void prepW(const float* __restrict__ mu, const float* __restrict__ log_cov) {
    int kl = blockIdx.x, t = threadIdx.x;
    const float* mu_r = mu + (size_t)kl * FDIM;
    const float* lc_r = log_cov + (size_t)kl * FDIM;

    float w[4], w2[4];
    float s_lc = 0.f, s_m2 = 0.f, am = 0.f;
#pragma unroll
    for (int j = 0; j < 4; j++) {
        int f = t * 4 + j;
        float lc = lc_r[f];
        float iv = expf(-lc);
        float m  = mu_r[f];
        w[j]  = m * iv;
        w2[j] = -0.5f * iv;
        s_lc += lc;
        s_m2 += m * m * iv;
        am = fmaxf(am, fabsf(w[j]));
    }
    __shared__ float sh0[256], sh1[256], shm[256];
    sh0[t] = s_lc; sh1[t] = s_m2; shm[t] = am;
    __syncthreads();
    for (int s = 128; s > 0; s >>= 1) {
        if (t < s) {
            sh0[t] += sh0[t + s];
            sh1[t] += sh1[t + s];
            shm[t] = fmaxf(shm[t], shm[t + s]);
        }
        __syncthreads();
    }
    float absmax = fmaxf(shm[0], 1e-20f);
    float inv = 127.0f / absmax;
    *reinterpret_cast<uint32_t*>(g_Wq + tiled_off(kl, t, 0)) =
        pack4(q8(w[0], inv), q8(w[1], inv), q8(w[2], inv), q8(w[3], inv));
    float inv2 = inv * ALPHA;
    *reinterpret_cast<uint32_t*>(g_Wq + tiled_off(kl, t, 1)) =
        pack4(q8(w2[0], inv2), q8(w2[1], inv2), q8(w2[2], inv2), q8(w2[3], inv2));
    if (t == 0) {
        g_sW[kl] = absmax / 127.0f;
        g_bias[kl] += -0.5f * (float)FDIM * 1.8378770664093453f - 0.5f * sh0[0] - 0.5f * sh1[0];
    }
}

// warp-per-row: absmax -> quantize X (+ X^2 if fallback), q[row], scale.
__global__ void prepA(const float* __restrict__ X) {
    int lane = threadIdx.x & 31;
    int row  = blockIdx.x * 8 + (threadIdx.x >> 5);
    bool uni = (g_uniform != 0);

    const float4* xr = reinterpret_cast<const float4*>(X) + (size_t)row * 256;
    float4 v[8];
    float am = 0.f;
#pragma unroll
    for (int j = 0; j < 8; j++) {
        v[j] = xr[lane + j * 32];
        am = fmaxf(am, fmaxf(fmaxf(fabsf(v[j].x), fabsf(v[j].y)),
                             fmaxf(fabsf(v[j].z), fabsf(v[j].w))));
    }
#pragma unroll
    for (int o = 16; o > 0; o >>= 1) am = fmaxf(am, __shfl_xor_sync(0xffffffffu, am, o));
    float absmax = fmaxf(am, 1e-20f);
    float inv = 127.0f / absmax;

    float q = 0.f;
#pragma unroll
    for (int j = 0; j < 8; j++) {
        int idx = lane + j * 32;
        *reinterpret_cast<uint32_t*>(g_Aq + tiled_off(row, idx, 0)) =
            pack4(q8(v[j].x, inv), q8(v[j].y, inv), q8(v[j].z, inv), q8(v[j].w, inv));
        if (uni) {
            const float4 w = reinterpret_cast<const float4*>(g_w2)[idx];
            q += v[j].x * v[j].x * w.x + v[j].y * v[j].y * w.y
               + v[j].z * v[j].z * w.z + v[j].w * v[j].w * w.w;
        } else {
            float inv2 = inv / ALPHA;
            *reinterpret_cast<uint32_t*>(g_Aq + tiled_off(row, idx, 1)) =
                pack4(q8(v[j].x * v[j].x, inv2), q8(v[j].y * v[j].y, inv2),
                      q8(v[j].z * v[j].z, inv2), q8(v[j].w * v[j].w, inv2));
        }
    }
#pragma unroll
    for (int o = 16; o > 0; o >>= 1) q += __shfl_xor_sync(0xffffffffu, q, o);
    if (lane == 0) {
        g_q[row]  = q;
        g_sA[row] = absmax / 127.0f;
    }
}

// ---------------------------------------------------------------- main kernel
// Block 128x128, 8 warps 4(M)x2(N), warp tile 32x64; bulk-copy producer with
// per-buffer full/empty mbarriers; smem-transposed shuffle-free epilogue.
__global__ __launch_bounds__(NTHREADS, 2)
void gmm_main(float* __restrict__ out) {
    extern __shared__ char smem[];
    uint32_t sb = smem_u32(smem);
    float2* sBW = reinterpret_cast<float2*>(smem + SM_BW_OFF);   // (bias, sW)

    int tid  = threadIdx.x;
    int wid  = tid >> 5, lane = tid & 31;
    int wm   = wid & 3;          // 4 warps over M -> 32 rows each
    int wn   = wid >> 2;         // 2 warps over N -> 64 cols each

    int rowBase = blockIdx.y * BM;
    int colBase = blockIdx.x * BN;
    int kIters  = (g_uniform != 0) ? 8 : 16;

    const int8_t* gA = g_Aq + (size_t)blockIdx.y * (16 * 16384);
    const int8_t* gB = g_Wq + (size_t)blockIdx.x * (16 * 16384);

    uint32_t mbF = sb + SM_MBAR_OFF;        // 3 full barriers
    uint32_t mbE = mbF + 24;                // 3 empty barriers
    if (tid == 0) {
#pragma unroll
        for (int s = 0; s < 3; s++) {
            MBAR_INIT(mbF + s * 8, 1);      // tx-based completion
            MBAR_INIT(mbE + s * 8, 8);      // one arrive per warp
        }
    }
    if (tid < BN) sBW[tid] = make_float2(g_bias[colBase + tid], g_sW[colBase + tid]);
    __syncthreads();

    // prologue: 3 stages in flight
    if (tid == 0) {
#pragma unroll
        for (int s = 0; s < 3; s++) {
            uint32_t mb = mbF + s * 8;
            uint32_t dst = sb + s * STAGE_BYTES;
            MBAR_EXPECT_TX(mb, STAGE_BYTES);
            BULK_G2S(dst,         gA + (size_t)s * 16384, 16384, mb);
            BULK_G2S(dst + 16384, gB + (size_t)s * 16384, 16384, mb);
        }
    }

    int acc[2][8][4];
#pragma unroll
    for (int mt = 0; mt < 2; mt++)
#pragma unroll
        for (int nt = 0; nt < 8; nt++)
#pragma unroll
            for (int j = 0; j < 4; j++) acc[mt][nt][j] = 0;

    // per-lane swizzled base offsets (XOR-composable with ks<<5)
    int cHi = lane >> 4;
    uint32_t offA[2], offB[4];
#pragma unroll
    for (int mt = 0; mt < 2; mt++) {
        int r = wm * 32 + (lane & 15) + mt * 16;
        offA[mt] = (uint32_t)(r * 128) + (uint32_t)(((cHi ^ (r & 7))) << 4);
    }
#pragma unroll
    for (int p = 0; p < 4; p++) {
        int r = wn * 64 + (lane & 15) + p * 16;
        offB[p] = (uint32_t)(16384 + r * 128) + (uint32_t)(((cHi ^ (r & 7))) << 4);
    }

    int phF0 = 0, phF1 = 0, phF2 = 0;
    int phE0 = 0, phE1 = 0, phE2 = 0;

#pragma unroll 1
    for (int s = 0; s < kIters; s++) {
        int b = s % 3;
        uint32_t fb = mbF + (uint32_t)b * 8;
        uint32_t eb = mbE + (uint32_t)b * 8;
        if (b == 0)      { MBAR_WAIT(fb, phF0); phF0 ^= 1; }
        else if (b == 1) { MBAR_WAIT(fb, phF1); phF1 ^= 1; }
        else             { MBAR_WAIT(fb, phF2); phF2 ^= 1; }

        uint32_t smStage = sb + (uint32_t)b * STAGE_BYTES;
        uint32_t bA0 = smStage + offA[0], bA1 = smStage + offA[1];
        uint32_t bB0 = smStage + offB[0], bB1 = smStage + offB[1];
        uint32_t bB2 = smStage + offB[2], bB3 = smStage + offB[3];

#pragma unroll
        for (int ks = 0; ks < 4; ks++) {       // each ks = 32 int8 k-elems
            uint32_t kx = (uint32_t)ks << 5;
            uint32_t a[2][4], bb[4][4];
            LDSM4(a[0], bA0 ^ kx);
            LDSM4(a[1], bA1 ^ kx);
            LDSM4(bb[0], bB0 ^ kx);
            LDSM4(bb[1], bB1 ^ kx);
            LDSM4(bb[2], bB2 ^ kx);
            LDSM4(bb[3], bB3 ^ kx);
#pragma unroll
            for (int mt = 0; mt < 2; mt++)
#pragma unroll
                for (int nt = 0; nt < 8; nt++) {
                    int p = nt >> 1, q = nt & 1;
                    MMAI8(acc[mt][nt], a[mt], bb[p][q], bb[p][q + 2]);
                }
        }

        // this warp is done reading buffer b (release-arrive)
        if (lane == 0) MBAR_ARRIVE(eb);

        // producer: wait for all 8 warps, then refill buffer b with stage s+3
        if (tid == 0 && s + 3 < kIters) {
            if (b == 0)      { MBAR_WAIT(eb, phE0); phE0 ^= 1; }
            else if (b == 1) { MBAR_WAIT(eb, phE1); phE1 ^= 1; }
            else             { MBAR_WAIT(eb, phE2); phE2 ^= 1; }
            uint32_t dst = sb + (uint32_t)b * STAGE_BYTES;
            MBAR_EXPECT_TX(fb, STAGE_BYTES);
            BULK_G2S(dst,         gA + (size_t)(s + 3) * 16384, 16384, fb);
            BULK_G2S(dst + 16384, gB + (size_t)(s + 3) * 16384, 16384, fb);
        }
    }

    // ------------- epilogue: smem transpose, in-lane logsumexp, no shuffles
    float* sLog = reinterpret_cast<float*>(smem);    // reuse stage buffers
    __syncthreads();                                 // all MMAs done, buffers dead

    int colq = (lane & 3) * 2;
#pragma unroll
    for (int mt = 0; mt < 2; mt++) {
#pragma unroll
        for (int h = 0; h < 2; h++) {
            int r = wm * 32 + mt * 16 + h * 8 + (lane >> 2);   // local row
            float sxr = g_sA[rowBase + r];
#pragma unroll
            for (int nt = 0; nt < 8; nt++) {
                int c0 = wn * 64 + nt * 8 + colq;
                float2 bw0 = sBW[c0];
                float2 bw1 = sBW[c0 + 1];
                float l0 = (float)acc[mt][nt][h * 2]     * (bw0.y * sxr) + bw0.x;
                float l1 = (float)acc[mt][nt][h * 2 + 1] * (bw1.y * sxr) + bw1.x;
                *reinterpret_cast<float2*>(sLog + r * EPITCH + c0) = make_float2(l0, l1);
            }
        }
    }
    __syncthreads();

    // LSE pass: thread t -> row t>>1, k-half t&1 -> 8 LSEs, contiguous reads
    {
        int r    = tid >> 1;
        int half = tid & 1;
        float qr = g_q[rowBase + r];
        const float* rowp = sLog + r * EPITCH + half * 64;
        float res[8];
#pragma unroll
        for (int j = 0; j < 8; j++) {
            float4 v0 = *reinterpret_cast<const float4*>(rowp + j * 8);
            float4 v1 = *reinterpret_cast<const float4*>(rowp + j * 8 + 4);
            float m = fmaxf(fmaxf(fmaxf(v0.x, v0.y), fmaxf(v0.z, v0.w)),
                            fmaxf(fmaxf(v1.x, v1.y), fmaxf(v1.z, v1.w)));
            float sum = fast_exp(v0.x - m) + fast_exp(v0.y - m)
                      + fast_exp(v0.z - m) + fast_exp(v0.w - m)
                      + fast_exp(v1.x - m) + fast_exp(v1.y - m)
                      + fast_exp(v1.z - m) + fast_exp(v1.w - m);
            res[j] = m + fast_log(sum) + qr;
        }
        float* orow = out + (size_t)(rowBase + r) * NK + (colBase >> 3) + half * 8;
        *reinterpret_cast<float4*>(orow)     = make_float4(res[0], res[1], res[2], res[3]);
        *reinterpret_cast<float4*>(orow + 4) = make_float4(res[4], res[5], res[6], res[7]);
    }
}

// ---------------------------------------------------------------- launch
extern "C" void kernel_launch(void* const* d_in, const int* in_sizes, int n_in,
                              void* d_out, int out_size) {
    const float* X       = (const float*)d_in[0];
    const float* mu      = (const float*)d_in[1];
    const float* log_cov = (const float*)d_in[2];
    const float* log_pi  = (const float*)d_in[3];
    float* out = (float*)d_out;

    cudaFuncSetAttribute(gmm_main, cudaFuncAttributeMaxDynamicSharedMemorySize, SMEM_TOTAL);

    prep0<<<KLD, 256>>>(log_cov, log_pi);
    prepW<<<KLD, 256>>>(mu, log_cov);
    prepA<<<BTD / 8, 256>>>(X);

    dim3 grid(KLD / BN, BTD / BM);   // (16, 256)
    gmm_main<<<grid, NTHREADS, SMEM_TOTAL>>>(out);
}